// round 16
// baseline (speedup 1.0000x reference)
#include <cuda_runtime.h>
#include <cuda_fp16.h>
#include <cstdint>

#define NPTS 8192
#define D 200
#define ROW_BYTES 512              // f16 rows zero-padded to 256 k in global
#define TM 128
#define NT (NPTS / TM)             // 64
#define NTRI (NT * (NT + 1) / 2)   // 2080
#define TPB 256
#define SROW 112                   // 96B chunk row + 16 pad -> conflict-free
#define ACH (TM * SROW)            // 14336
#define STAGE (2 * ACH)            // A + B per stage = 28672
#define SMEM_DYN (2 * STAGE)       // double buffer = 57344; 3 CTAs/SM = 172KB

// ---------------- device scratch (no allocations allowed) ----------------
__device__ __align__(16) unsigned char g_xb[(size_t)NPTS * ROW_BYTES]; // 4 MB f16
__device__ float g_sq[NPTS];
__device__ float g_part[NTRI];
__device__ int   g_is64;
__device__ unsigned int g_cnt;

#define CP16(d, s) \
    asm volatile("cp.async.cg.shared.global [%0], [%1], 16;" :: "r"(d), "l"(s) : "memory")
#define CPC()  asm volatile("cp.async.commit_group;" ::: "memory")
#define CPW1() asm volatile("cp.async.wait_group 1;" ::: "memory")
#define CPW0() asm volatile("cp.async.wait_group 0;" ::: "memory")

// ---------------------------------------------------------------------------
// Kernel 1: x -> f16 (zero-padded), sq from the SAME f16 values.
// Block 0 additionally: label-dtype detection + counter reset.
// ---------------------------------------------------------------------------
__global__ void prep_kernel(const float* __restrict__ x,
                            const int* __restrict__ lab32) {
    int row  = blockIdx.x * (TPB / 32) + (threadIdx.x >> 5);
    int lane = threadIdx.x & 31;
    int k0   = lane * 8;
    const float* xr = x + (size_t)row * D;
    float s = 0.f;
    uint32_t w[4];
#pragma unroll
    for (int p = 0; p < 4; p++) {
        int ka = k0 + 2 * p, kb = ka + 1;
        float f0 = (ka < D) ? xr[ka] : 0.f;
        float f1 = (kb < D) ? xr[kb] : 0.f;
        __half h0 = __float2half(f0);
        __half h1 = __float2half(f1);
        float g0 = __half2float(h0), g1 = __half2float(h1);
        s = fmaf(g0, g0, s);
        s = fmaf(g1, g1, s);
        w[p] = (uint32_t)__half_as_ushort(h0) |
               ((uint32_t)__half_as_ushort(h1) << 16);
    }
    *(uint4*)(g_xb + (size_t)row * ROW_BYTES + k0 * 2) = make_uint4(w[0], w[1], w[2], w[3]);
#pragma unroll
    for (int o = 16; o; o >>= 1) s += __shfl_xor_sync(0xffffffffu, s, o);
    if (lane == 0) g_sq[row] = s;

    if (blockIdx.x == 0) {  // label dtype detection + counter reset
        __shared__ int any;
        if (threadIdx.x == 0) { any = 0; g_cnt = 0; }
        __syncthreads();
        int a = 0;
        for (int i = 2 * threadIdx.x + 1; i < NPTS; i += 2 * TPB) a |= lab32[i];
        if (a) atomicOr(&any, 1);
        __syncthreads();
        if (threadIdx.x == 0) g_is64 = (any == 0) ? 1 : 0;
    }
}

// ---------------------------------------------------------------------------
// Chunk prefetch: 96B of K per row for A(128) + B(128) rows into stage buf.
// (Last chunk reads padded zeros beyond k=208 - harmless, keeps code uniform.)
// ---------------------------------------------------------------------------
__device__ __forceinline__ void prefetch(uint32_t dynA, int buf,
                                         const unsigned char* gA,
                                         const unsigned char* gB, int ch, int t) {
    int row = t & 127, op = t >> 7;
    const unsigned char* src = (op ? gB : gA) + (size_t)row * ROW_BYTES + (size_t)ch * 96;
    uint32_t dst = dynA + (buf ? (uint32_t)STAGE : 0u) + (op ? (uint32_t)ACH : 0u)
                 + row * SROW;
#pragma unroll
    for (int c = 0; c < 6; c++)
        CP16(dst + c * 16, src + c * 16);
    CPC();
}

// ---------------------------------------------------------------------------
// Kernel 2: triangular grid of 128x128 Gram tiles, mma.sync f16 m16n8k16
// with f16 accumulators (2-reg C frags -> 3 CTAs/SM). R13-style explicit
// fragment pipeline; 5 chunks of 3/3/3/3/1 k-steps.
// ---------------------------------------------------------------------------
__global__ void __launch_bounds__(TPB, 3)
pair_kernel(const int* __restrict__ lab32, float* __restrict__ out) {
    extern __shared__ __align__(128) unsigned char dyn[];
    __shared__ float sqA[TM], sqB[TM];
    __shared__ int   lA[TM], lB[TM];
    __shared__ float red[TPB / 32];
    __shared__ int    s_last;
    __shared__ double dred[TPB];

    const int t    = threadIdx.x;
    const int wid  = t >> 5;
    const int lane = t & 31;

    // linearized upper-triangle map: blockIdx.x -> (ti, tj), ti <= tj
    int bl = blockIdx.x, ti = 0;
    while (bl >= NT - ti) { bl -= NT - ti; ti++; }
    const int tj = ti + bl;

    const uint32_t dynA = (uint32_t)__cvta_generic_to_shared(dyn);
    const unsigned char* gA = g_xb + (size_t)(ti * TM) * ROW_BYTES;
    const unsigned char* gB = g_xb + (size_t)(tj * TM) * ROW_BYTES;

    prefetch(dynA, 0, gA, gB, 0, t);
    prefetch(dynA, 1, gA, gB, 1, t);

    {
        int is64 = g_is64;
        if (t < TM) {
            int g = ti * TM + t;
            sqA[t] = g_sq[g];
            lA[t]  = is64 ? lab32[2 * g] : lab32[g];
        } else {
            int u = t - TM, g = tj * TM + u;
            sqB[u] = g_sq[g];
            lB[u]  = is64 ? lab32[2 * g] : lab32[g];
        }
    }

    const int warp_m = wid >> 1;   // 0..3 -> 32 rows
    const int warp_n = wid & 1;    // 0..1 -> 64 cols

    // Padded-stride (conflict-free) immediate-offset ldmatrix bases.
    uint32_t abase[2];
#pragma unroll
    for (int f = 0; f < 2; f++)
        abase[f] = dynA + (warp_m * 32 + f * 16 + (lane & 15)) * SROW
                 + ((lane >> 4) << 4);
    uint32_t bbase[4];
#pragma unroll
    for (int h = 0; h < 4; h++)
        bbase[h] = dynA + ACH
                 + (warp_n * 64 + h * 16 + (lane & 7) + ((lane >> 4) << 3)) * SROW
                 + (((lane >> 3) & 1) << 4);

    uint32_t acc[2][8][2];   // f16x2 accumulators: [f][j][{rows r, r+8}]
#pragma unroll
    for (int f = 0; f < 2; f++)
#pragma unroll
        for (int j = 0; j < 8; j++) {
            acc[f][j][0] = 0u;
            acc[f][j][1] = 0u;
        }

    uint32_t aF[2][2][4];   // [kstep parity][f][frag]
    uint32_t bF[2][4];      // [stage parity][frag]

#define LDA_M(buf, kk)                                                            \
    { _Pragma("unroll")                                                           \
      for (int f = 0; f < 2; f++)                                                 \
          asm volatile("ldmatrix.sync.aligned.m8n8.x4.shared.b16 {%0,%1,%2,%3}, [%4];" \
              : "=r"(aF[buf][f][0]), "=r"(aF[buf][f][1]),                         \
                "=r"(aF[buf][f][2]), "=r"(aF[buf][f][3])                          \
              : "r"(abase[f] + bofs + (kk) * 32)); }

#define LDB_M(slot, kk, hh)                                                       \
    asm volatile("ldmatrix.sync.aligned.m8n8.x4.shared.b16 {%0,%1,%2,%3}, [%4];"  \
        : "=r"(bF[slot][0]), "=r"(bF[slot][1]), "=r"(bF[slot][2]), "=r"(bF[slot][3]) \
        : "r"(bbase[hh] + bofs + (kk) * 32))

#define MMA4_M(abuf, slot, hh)                                                    \
    { _Pragma("unroll")                                                           \
      for (int f = 0; f < 2; f++) {                                               \
          asm volatile(                                                           \
              "mma.sync.aligned.m16n8k16.row.col.f16.f16.f16.f16 "                \
              "{%0,%1}, {%2,%3,%4,%5}, {%6,%7}, {%0,%1};"                         \
              : "+r"(acc[f][2 * (hh)][0]), "+r"(acc[f][2 * (hh)][1])              \
              : "r"(aF[abuf][f][0]), "r"(aF[abuf][f][1]),                         \
                "r"(aF[abuf][f][2]), "r"(aF[abuf][f][3]),                         \
                "r"(bF[slot][0]), "r"(bF[slot][1]));                              \
          asm volatile(                                                           \
              "mma.sync.aligned.m16n8k16.row.col.f16.f16.f16.f16 "                \
              "{%0,%1}, {%2,%3,%4,%5}, {%6,%7}, {%0,%1};"                         \
              : "+r"(acc[f][2 * (hh) + 1][0]), "+r"(acc[f][2 * (hh) + 1][1])      \
              : "r"(aF[abuf][f][0]), "r"(aF[abuf][f][1]),                         \
                "r"(aF[abuf][f][2]), "r"(aF[abuf][f][3]),                         \
                "r"(bF[slot][2]), "r"(bF[slot][3]));                              \
      } }

// Pipelined chunk: NS ksteps = 4*NS h-stages; LDSM for s+1 precedes MMA for s.
#define CHUNK_M(NS)                                                               \
    do {                                                                          \
        LDA_M(0, 0);                                                              \
        LDB_M(0, 0, 0);                                                           \
        _Pragma("unroll")                                                         \
        for (int s = 0; s < 4 * (NS); s++) {                                      \
            int ks = s >> 2, h = s & 3;                                           \
            int sn = s + 1, kn = sn >> 2, hn = sn & 3;                            \
            if (sn < 4 * (NS)) {                                                  \
                if (hn == 0) LDA_M(kn & 1, kn);                                   \
                LDB_M(sn & 1, kn, hn);                                            \
            }                                                                     \
            MMA4_M(ks & 1, s & 1, h);                                             \
        }                                                                         \
    } while (0)

#pragma unroll
    for (int ch = 0; ch < 5; ch++) {
        if (ch < 4) CPW1(); else CPW0();
        __syncthreads();
        const uint32_t bofs = (ch & 1) ? (uint32_t)STAGE : 0u;
        if (ch < 4) CHUNK_M(3); else CHUNK_M(1);   // 13 k-steps total
        __syncthreads();
        if (ch < 3) prefetch(dynA, ch & 1, gA, gB, ch + 2, t);
    }
#undef CHUNK_M
#undef MMA4_M
#undef LDB_M
#undef LDA_M

    // ---- Epilogue: unpack f16x2, hoist sA4/lA4, diag/off-diag split ----
    const int qrow = lane >> 2;
    const int qcol = (lane & 3) * 2;
    float sA4[4]; int lA4[4];
#pragma unroll
    for (int r = 0; r < 4; r++) {
        int m = warp_m * 32 + (r >> 1) * 16 + (r & 1) * 8 + qrow;
        sA4[r] = sqA[m];
        lA4[r] = lA[m];
    }
    float ps[4] = {0.f, 0.f, 0.f, 0.f};
    if (ti != tj) {  // 2016/2080 tiles: no predicate, no fmax, no index math
#pragma unroll
        for (int f = 0; f < 2; f++)
#pragma unroll
            for (int j = 0; j < 8; j++) {
                int n0 = warp_n * 64 + j * 8 + qcol;
#pragma unroll
                for (int rr = 0; rr < 2; rr++) {
                    int r = f * 2 + rr;
                    float2 v = __half22float2(*(__half2*)&acc[f][j][rr]);
                    float d2a = fmaf(-2.f, v.x, sA4[r] + sqB[n0]);
                    float d2b = fmaf(-2.f, v.y, sA4[r] + sqB[n0 + 1]);
                    float da, db;
                    asm("sqrt.approx.f32 %0, %1;" : "=f"(da) : "f"(d2a));
                    asm("sqrt.approx.f32 %0, %1;" : "=f"(db) : "f"(d2b));
                    ps[rr * 2]     += (lA4[r] == lB[n0])     ? da : -da;
                    ps[rr * 2 + 1] += (lA4[r] == lB[n0 + 1]) ? db : -db;
                }
            }
    } else {         // 64 diagonal tiles: strict upper predicate + clamp
#pragma unroll
        for (int f = 0; f < 2; f++)
#pragma unroll
            for (int j = 0; j < 8; j++) {
                int n0 = warp_n * 64 + j * 8 + qcol;
#pragma unroll
                for (int rr = 0; rr < 2; rr++) {
                    int r = f * 2 + rr;
                    int m_loc = warp_m * 32 + f * 16 + rr * 8 + qrow;
                    float2 v = __half22float2(*(__half2*)&acc[f][j][rr]);
#pragma unroll
                    for (int cc = 0; cc < 2; cc++) {
                        int n = n0 + cc;
                        float g = cc ? v.y : v.x;
                        float d2 = fmaxf(fmaf(-2.f, g, sA4[r] + sqB[n]), 0.f);
                        float dist;
                        asm("sqrt.approx.f32 %0, %1;" : "=f"(dist) : "f"(d2));
                        float sgn = (lA4[r] == lB[n]) ? dist : -dist;
                        if (n > m_loc) ps[rr * 2 + cc] += sgn;
                    }
                }
            }
    }
    float lsum = (ps[0] + ps[1]) + (ps[2] + ps[3]);
#pragma unroll
    for (int o = 16; o; o >>= 1) lsum += __shfl_xor_sync(0xffffffffu, lsum, o);
    if (lane == 0) red[wid] = lsum;
    __syncthreads();
    if (t == 0) {
        float s = 0.f;
#pragma unroll
        for (int w = 0; w < TPB / 32; w++) s += red[w];
        g_part[blockIdx.x] = s;
    }

    // ---- last-CTA-done fused final reduction (deterministic order) ----
    __threadfence();
    if (t == 0) {
        unsigned old = atomicAdd(&g_cnt, 1u);
        s_last = (old == NTRI - 1) ? 1 : 0;
    }
    __syncthreads();
    if (s_last) {
        __threadfence();
        double a = 0.0;
        for (int i = t; i < NTRI; i += TPB) a += (double)g_part[i];
        dred[t] = a;
        __syncthreads();
        for (int o = TPB / 2; o; o >>= 1) {
            if (t < o) dred[t] += dred[t + o];
            __syncthreads();
        }
        if (t == 0) out[0] = (float)(2.0 * dred[0] / (double)NPTS);
    }
}

// ---------------------------------------------------------------------------
extern "C" void kernel_launch(void* const* d_in, const int* in_sizes, int n_in,
                              void* d_out, int out_size) {
    const float* x     = (const float*)d_in[0];
    const int*   lab32 = (const int*)d_in[1];
    float*       outp  = (float*)d_out;

    cudaFuncSetAttribute(pair_kernel, cudaFuncAttributeMaxDynamicSharedMemorySize,
                         SMEM_DYN);

    prep_kernel<<<NPTS / (TPB / 32), TPB>>>(x, lab32);
    pair_kernel<<<NTRI, TPB, SMEM_DYN>>>(lab32, outp);
}